// round 1
// baseline (speedup 1.0000x reference)
#include <cuda_runtime.h>
#include <math.h>

#define DTF 1e-4f
#define LN_EPS 1e-5f

constexpr int Bb = 16;    // batch
constexpr int S  = 4096;  // sequence
constexpr int D  = 256;   // model dim
constexpr int N  = 16;    // state dim
constexpr int L  = 128;   // chunk length
constexpr int NC = S / L; // 32 chunks per batch

// Scratch (no cudaMalloc allowed): local prefix states p_t, per-chunk carries, chunk input states
__device__ float g_p[Bb * S * N];        // 4 MB
__device__ float g_carry[Bb * NC * N];
__device__ float g_hin[Bb * NC * N];

__device__ __forceinline__ float clip10(float v) {
    return fminf(fmaxf(v, -10.0f), 10.0f);
}

// ---------------------------------------------------------------------------
// Kernel A: W = (DT*Bm) @ u per timestep, then local (within-chunk) scan
//   p_j = A_d * p_{j-1} + w_j, p_{-1} = 0.  Stores p_t and per-chunk carry.
// ---------------------------------------------------------------------------
__global__ void __launch_bounds__(256) kA(const float* __restrict__ x,
                                          const float* __restrict__ A,
                                          const float* __restrict__ Bm) {
    __shared__ float bd[D * 17];   // bd[d*17 + n] = DT*Bm[n][d]; stride 17 => conflict-free
    __shared__ float Wbuf[L * N];

    const int c = blockIdx.x, b = blockIdx.y;
    const int tid = threadIdx.x, lane = tid & 31, warp = tid >> 5;

    for (int idx = tid; idx < N * D; idx += 256) {
        int n = idx >> 8;      // Bm is [N][D] row-major
        int d = idx & 255;
        bd[d * 17 + n] = DTF * Bm[idx];
    }
    __syncthreads();

    const float* xbase = x + (size_t)(b * S + c * L) * D;

    // warp handles rows j = warp*16 .. warp*16+15
    for (int i = 0; i < 16; i++) {
        const int j = warp * 16 + i;
        const float* xr = xbase + (size_t)j * D;

        float xv[8];
        #pragma unroll
        for (int k = 0; k < 8; k++) xv[k] = xr[lane + 32 * k];

        float a[16];
        #pragma unroll
        for (int n = 0; n < 16; n++) a[n] = 0.f;

        #pragma unroll
        for (int k = 0; k < 8; k++) {
            const int base = (lane + 32 * k) * 17;
            const float xk = xv[k];
            #pragma unroll
            for (int n = 0; n < 16; n++) a[n] = fmaf(xk, bd[base + n], a[n]);
        }

        // Multi-value warp reduction: 16 accumulators -> lane pairs, 16 shfl total.
        {
            const bool hb = (lane & 16) != 0;
            #pragma unroll
            for (int t = 0; t < 8; t++) {
                float keep = hb ? a[t + 8] : a[t];
                float send = hb ? a[t] : a[t + 8];
                a[t] = keep + __shfl_xor_sync(0xffffffffu, send, 16);
            }
        }
        {
            const bool hb = (lane & 8) != 0;
            #pragma unroll
            for (int t = 0; t < 4; t++) {
                float keep = hb ? a[t + 4] : a[t];
                float send = hb ? a[t] : a[t + 4];
                a[t] = keep + __shfl_xor_sync(0xffffffffu, send, 8);
            }
        }
        {
            const bool hb = (lane & 4) != 0;
            #pragma unroll
            for (int t = 0; t < 2; t++) {
                float keep = hb ? a[t + 2] : a[t];
                float send = hb ? a[t] : a[t + 2];
                a[t] = keep + __shfl_xor_sync(0xffffffffu, send, 4);
            }
        }
        {
            const bool hb = (lane & 2) != 0;
            float keep = hb ? a[1] : a[0];
            float send = hb ? a[0] : a[1];
            a[0] = keep + __shfl_xor_sync(0xffffffffu, send, 2);
        }
        a[0] += __shfl_xor_sync(0xffffffffu, a[0], 1);

        // lane bits [4:1] encode n; even lanes write
        if ((lane & 1) == 0) Wbuf[j * 16 + ((lane >> 1) & 15)] = a[0];
    }
    __syncthreads();

    // Local sequential scan over the chunk (16 lanes, one per n)
    if (warp == 0 && lane < 16) {
        const float Ad = expf(-DTF * fabsf(A[lane]));  // == 1.0f for these inputs
        float p = 0.f;
        #pragma unroll 4
        for (int j = 0; j < L; j++) {
            p = fmaf(p, Ad, Wbuf[j * 16 + lane]);
            Wbuf[j * 16 + lane] = p;
        }
        g_carry[(b * NC + c) * N + lane] = p;
    }
    __syncthreads();

    float* pg = g_p + (size_t)(b * S + c * L) * N;
    for (int idx = tid; idx < L * N; idx += 256) pg[idx] = Wbuf[idx];
}

// ---------------------------------------------------------------------------
// Kernel B: inter-chunk carry scan.  h_in[c] = A_d^L * h_in[c-1] + carry[c-1]
// One block, thread = (batch, n).  Carries prefetched for MLP.
// ---------------------------------------------------------------------------
__global__ void kB(const float* __restrict__ A) {
    const int tid = threadIdx.x;
    const int b = tid >> 4, n = tid & 15;
    const float Ad = expf(-DTF * fabsf(A[n]));
    float AL = Ad;
    #pragma unroll
    for (int i = 0; i < 7; i++) AL *= AL;   // Ad^128

    float ca[NC];
    #pragma unroll
    for (int c = 0; c < NC; c++) ca[c] = g_carry[(b * NC + c) * N + n];

    float h = 0.f;
    #pragma unroll
    for (int c = 0; c < NC; c++) {
        g_hin[(b * NC + c) * N + n] = h;
        h = fmaf(h, AL, ca[c]);
    }
}

// ---------------------------------------------------------------------------
// Kernel C: h_t = A^(j+1)*h_in + p_t (clip), y = h@Cm^T + u*Dv (clip), LayerNorm.
// Warp per row => LayerNorm needs only warp shuffles, no block sync in hot loop.
// ---------------------------------------------------------------------------
__global__ void __launch_bounds__(256) kC(const float* __restrict__ x,
                                          const float* __restrict__ A,
                                          const float* __restrict__ Cm,
                                          const float* __restrict__ Dv,
                                          const float* __restrict__ gamma,
                                          const float* __restrict__ beta,
                                          float* __restrict__ out) {
    __shared__ float cms[D * 17];  // cms[d*17 + n] = Cm[d][n]; conflict-free for d = lane+32k
    __shared__ float dvs[D], gs[D], bs[D];
    __shared__ float apw[L * N];   // A_d^(j+1)

    const int c = blockIdx.x, b = blockIdx.y;
    const int tid = threadIdx.x, lane = tid & 31, warp = tid >> 5;

    for (int idx = tid; idx < D * N; idx += 256)
        cms[(idx >> 4) * 17 + (idx & 15)] = Cm[idx];    // Cm is [D][N] row-major
    if (tid < D) { dvs[tid] = Dv[tid]; gs[tid] = gamma[tid]; bs[tid] = beta[tid]; }
    if (tid < 16) {
        const float Ad = expf(-DTF * fabsf(A[tid]));
        float p = 1.f;
        for (int j = 0; j < L; j++) { p *= Ad; apw[j * 16 + tid] = p; }
    }
    __syncthreads();

    float hin = 0.f;
    if (lane < 16) hin = g_hin[(b * NC + c) * N + lane];

    for (int i = 0; i < L / 8; i++) {
        const int j = i * 8 + warp;
        const size_t row = (size_t)(b * S) + c * L + j;

        float hn = 0.f;
        if (lane < 16) {
            const float pv = g_p[row * N + lane];
            hn = clip10(fmaf(apw[j * 16 + lane], hin, pv));
        }

        const float* xr = x + row * D;
        float y[8];
        #pragma unroll
        for (int k = 0; k < 8; k++) {
            const int d = lane + 32 * k;
            y[k] = xr[d] * dvs[d];
        }

        #pragma unroll
        for (int n = 0; n < 16; n++) {
            const float hb = __shfl_sync(0xffffffffu, hn, n);
            #pragma unroll
            for (int k = 0; k < 8; k++)
                y[k] = fmaf(hb, cms[(lane + 32 * k) * 17 + n], y[k]);
        }

        float s = 0.f, ss = 0.f;
        #pragma unroll
        for (int k = 0; k < 8; k++) {
            y[k] = clip10(y[k]);
            s += y[k];
            ss = fmaf(y[k], y[k], ss);
        }
        #pragma unroll
        for (int off = 16; off >= 1; off >>= 1) {
            s  += __shfl_xor_sync(0xffffffffu, s, off);
            ss += __shfl_xor_sync(0xffffffffu, ss, off);
        }
        const float mu  = s * (1.0f / 256.0f);
        const float var = fmaf(ss, 1.0f / 256.0f, -mu * mu);
        const float r   = rsqrtf(var + LN_EPS);

        float* orow = out + row * D;
        #pragma unroll
        for (int k = 0; k < 8; k++) {
            const int d = lane + 32 * k;
            orow[d] = fmaf((y[k] - mu) * r, gs[d], bs[d]);
        }
    }
}

extern "C" void kernel_launch(void* const* d_in, const int* in_sizes, int n_in,
                              void* d_out, int out_size) {
    const float* x     = (const float*)d_in[0];
    const float* A     = (const float*)d_in[1];
    const float* Bm    = (const float*)d_in[2];
    const float* Cm    = (const float*)d_in[3];
    const float* Dv    = (const float*)d_in[4];
    const float* gamma = (const float*)d_in[5];
    const float* beta  = (const float*)d_in[6];
    float* out = (float*)d_out;

    kA<<<dim3(NC, Bb), 256>>>(x, A, Bm);
    kB<<<1, 256>>>(A);
    kC<<<dim3(NC, Bb), 256>>>(x, A, Cm, Dv, gamma, beta, out);
}

// round 2
// speedup vs baseline: 1.1054x; 1.1054x over previous
#include <cuda_runtime.h>
#include <math.h>

#define DTF 1e-4f
#define LN_EPS 1e-5f

constexpr int Bb = 16;    // batch
constexpr int S  = 4096;  // sequence
constexpr int D  = 256;   // model dim
constexpr int N  = 16;    // state dim
constexpr int L  = 128;   // chunk length
constexpr int NC = S / L; // 32 chunks per batch

__device__ float g_p[Bb * S * N];        // local prefix states (4 MB)
__device__ float g_carry[Bb * NC * N];   // per-chunk carries

__device__ __forceinline__ float clip10(float v) {
    return fminf(fmaxf(v, -10.0f), 10.0f);
}

// Multi-value warp reduction: 16 accumulators spread over 32 lanes.
// Result valid on even lanes; n = (lane>>1)&15.
__device__ __forceinline__ float mv_reduce16(float a[16], int lane) {
    {
        const bool hb = (lane & 16) != 0;
        #pragma unroll
        for (int t = 0; t < 8; t++) {
            float keep = hb ? a[t + 8] : a[t];
            float send = hb ? a[t] : a[t + 8];
            a[t] = keep + __shfl_xor_sync(0xffffffffu, send, 16);
        }
    }
    {
        const bool hb = (lane & 8) != 0;
        #pragma unroll
        for (int t = 0; t < 4; t++) {
            float keep = hb ? a[t + 4] : a[t];
            float send = hb ? a[t] : a[t + 4];
            a[t] = keep + __shfl_xor_sync(0xffffffffu, send, 8);
        }
    }
    {
        const bool hb = (lane & 4) != 0;
        #pragma unroll
        for (int t = 0; t < 2; t++) {
            float keep = hb ? a[t + 2] : a[t];
            float send = hb ? a[t] : a[t + 2];
            a[t] = keep + __shfl_xor_sync(0xffffffffu, send, 4);
        }
    }
    {
        const bool hb = (lane & 2) != 0;
        float keep = hb ? a[1] : a[0];
        float send = hb ? a[0] : a[1];
        a[0] = keep + __shfl_xor_sync(0xffffffffu, send, 2);
    }
    a[0] += __shfl_xor_sync(0xffffffffu, a[0], 1);
    return a[0];
}

// ---------------------------------------------------------------------------
// Kernel A: W = (DT*Bm) @ u, row-pair tiled; then parallel 2-level local scan.
// ---------------------------------------------------------------------------
__global__ void __launch_bounds__(256, 2) kA(const float* __restrict__ x,
                                             const float* __restrict__ A,
                                             const float* __restrict__ Bm) {
    __shared__ float bd[D * 17];    // bd[d*17+n] = DT*Bm[n][d]; stride 17 => conflict-free
    __shared__ float Wbuf[L * N];
    __shared__ float sub[8 * N];
    __shared__ float pre[8 * N];

    const int c = blockIdx.x, b = blockIdx.y;
    const int tid = threadIdx.x, lane = tid & 31, warp = tid >> 5;

    for (int idx = tid; idx < N * D; idx += 256) {
        int n = idx >> 8;          // Bm is [N][D] row-major
        int d = idx & 255;
        bd[d * 17 + n] = DTF * Bm[idx];
    }
    __syncthreads();

    const float* xbase = x + (size_t)(b * S + c * L) * D;

    // Each warp computes its 16 rows as 8 pairs; each bd smem read feeds 2 FMAs.
    #pragma unroll 1
    for (int i = 0; i < 8; i++) {
        const int j0 = warp * 16 + i * 2;
        const float* xr0 = xbase + (size_t)j0 * D;
        const float* xr1 = xr0 + D;

        float xv0[8], xv1[8];
        #pragma unroll
        for (int k = 0; k < 8; k++) {
            xv0[k] = xr0[lane + 32 * k];
            xv1[k] = xr1[lane + 32 * k];
        }

        float a0[16], a1[16];
        #pragma unroll
        for (int n = 0; n < 16; n++) { a0[n] = 0.f; a1[n] = 0.f; }

        #pragma unroll
        for (int k = 0; k < 8; k++) {
            const int base = (lane + 32 * k) * 17;
            const float x0 = xv0[k], x1 = xv1[k];
            #pragma unroll
            for (int n = 0; n < 16; n++) {
                const float bv = bd[base + n];
                a0[n] = fmaf(x0, bv, a0[n]);
                a1[n] = fmaf(x1, bv, a1[n]);
            }
        }

        const float r0 = mv_reduce16(a0, lane);
        const float r1 = mv_reduce16(a1, lane);
        if ((lane & 1) == 0) {
            const int n = (lane >> 1) & 15;
            Wbuf[j0 * 16 + n]       = r0;
            Wbuf[(j0 + 1) * 16 + n] = r1;
        }
    }
    __syncwarp();

    // Level-1 scan: each warp scans its own 16 rows (lanes 0..15, one per n).
    float Ad = 0.f;
    if (lane < 16) {
        Ad = expf(-DTF * fabsf(A[lane]));
        float p = 0.f;
        #pragma unroll
        for (int r = 0; r < 16; r++) {
            const int j = warp * 16 + r;
            p = fmaf(p, Ad, Wbuf[j * 16 + lane]);
            Wbuf[j * 16 + lane] = p;
        }
        sub[warp * 16 + lane] = p;
    }
    __syncthreads();

    // Level-2 scan: warp 0 combines the 8 sub-carries (exclusive prefixes).
    if (warp == 0 && lane < 16) {
        float AL16 = Ad;
        #pragma unroll
        for (int t = 0; t < 4; t++) AL16 *= AL16;   // Ad^16
        float run = 0.f;
        #pragma unroll
        for (int w = 0; w < 8; w++) {
            pre[w * 16 + lane] = run;
            run = fmaf(run, AL16, sub[w * 16 + lane]);
        }
        g_carry[(b * NC + c) * N + lane] = run;
    }
    __syncthreads();

    // Apply prefix: p[16w+r] += Ad^(r+1) * pre[w]
    if (lane < 16 && warp > 0) {
        const float pref = pre[warp * 16 + lane];
        float f = Ad;
        #pragma unroll
        for (int r = 0; r < 16; r++) {
            const int j = warp * 16 + r;
            Wbuf[j * 16 + lane] = fmaf(f, pref, Wbuf[j * 16 + lane]);
            f *= Ad;
        }
    }
    __syncthreads();

    // Vectorized store of p to gmem
    float4* pg = reinterpret_cast<float4*>(g_p + (size_t)(b * S + c * L) * N);
    const float4* wb = reinterpret_cast<const float4*>(Wbuf);
    for (int idx = tid; idx < L * N / 4; idx += 256) pg[idx] = wb[idx];
}

// ---------------------------------------------------------------------------
// Kernel C: carry prefix (fused kB) + h_t + y + LayerNorm, row-pair tiled.
// ---------------------------------------------------------------------------
__global__ void __launch_bounds__(256, 2) kC(const float* __restrict__ x,
                                             const float* __restrict__ A,
                                             const float* __restrict__ Cm,
                                             const float* __restrict__ Dv,
                                             const float* __restrict__ gamma,
                                             const float* __restrict__ beta,
                                             float* __restrict__ out) {
    __shared__ float cms[D * 17];   // cms[d*17+n] = Cm[d][n]
    __shared__ float dvs[D], gs[D], bs[D];
    __shared__ float apw[L * N];    // Ad^(j+1)
    __shared__ float hin_s[N];

    const int c = blockIdx.x, b = blockIdx.y;
    const int tid = threadIdx.x, lane = tid & 31, warp = tid >> 5;

    for (int idx = tid; idx < D * N; idx += 256)
        cms[(idx >> 4) * 17 + (idx & 15)] = Cm[idx];   // Cm is [D][N]
    if (tid < D) { dvs[tid] = Dv[tid]; gs[tid] = gamma[tid]; bs[tid] = beta[tid]; }
    if (warp == 0 && lane < 16) {
        const float Ad = expf(-DTF * fabsf(A[lane]));
        float p = 1.f;
        for (int j = 0; j < L; j++) { p *= Ad; apw[j * 16 + lane] = p; }
    }
    // Inter-chunk carry prefix (was kernel B) — warp 1 does it while others stage.
    if (warp == 1 && lane < 16) {
        const float Ad = expf(-DTF * fabsf(A[lane]));
        float AL = Ad;
        #pragma unroll
        for (int t = 0; t < 7; t++) AL *= AL;   // Ad^128
        float h = 0.f;
        for (int cc = 0; cc < c; cc++)
            h = fmaf(h, AL, g_carry[(b * NC + cc) * N + lane]);
        hin_s[lane] = h;
    }
    __syncthreads();

    const float hin = (lane < 16) ? hin_s[lane] : 0.f;

    #pragma unroll 1
    for (int i = 0; i < 8; i++) {
        const int j0 = warp * 16 + i * 2;
        const size_t row0 = (size_t)(b * S) + c * L + j0;

        float hn0 = 0.f, hn1 = 0.f;
        if (lane < 16) {
            const float pv0 = g_p[row0 * N + lane];
            const float pv1 = g_p[(row0 + 1) * N + lane];
            hn0 = clip10(fmaf(apw[j0 * 16 + lane], hin, pv0));
            hn1 = clip10(fmaf(apw[(j0 + 1) * 16 + lane], hin, pv1));
        }

        const float* xr0 = x + row0 * D;
        const float* xr1 = xr0 + D;
        float y0[8], y1[8];
        #pragma unroll
        for (int k = 0; k < 8; k++) {
            const int d = lane + 32 * k;
            y0[k] = xr0[d] * dvs[d];
            y1[k] = xr1[d] * dvs[d];
        }

        #pragma unroll
        for (int n = 0; n < 16; n++) {
            const float hb0 = __shfl_sync(0xffffffffu, hn0, n);
            const float hb1 = __shfl_sync(0xffffffffu, hn1, n);
            #pragma unroll
            for (int k = 0; k < 8; k++) {
                const float cv = cms[(lane + 32 * k) * 17 + n];
                y0[k] = fmaf(hb0, cv, y0[k]);
                y1[k] = fmaf(hb1, cv, y1[k]);
            }
        }

        float s0 = 0.f, ss0 = 0.f, s1 = 0.f, ss1 = 0.f;
        #pragma unroll
        for (int k = 0; k < 8; k++) {
            y0[k] = clip10(y0[k]);
            y1[k] = clip10(y1[k]);
            s0 += y0[k];  ss0 = fmaf(y0[k], y0[k], ss0);
            s1 += y1[k];  ss1 = fmaf(y1[k], y1[k], ss1);
        }
        #pragma unroll
        for (int off = 16; off >= 1; off >>= 1) {
            s0  += __shfl_xor_sync(0xffffffffu, s0, off);
            ss0 += __shfl_xor_sync(0xffffffffu, ss0, off);
            s1  += __shfl_xor_sync(0xffffffffu, s1, off);
            ss1 += __shfl_xor_sync(0xffffffffu, ss1, off);
        }
        const float mu0 = s0 * (1.0f / 256.0f);
        const float r0v = rsqrtf(fmaf(ss0, 1.0f / 256.0f, -mu0 * mu0) + LN_EPS);
        const float mu1 = s1 * (1.0f / 256.0f);
        const float r1v = rsqrtf(fmaf(ss1, 1.0f / 256.0f, -mu1 * mu1) + LN_EPS);

        float* o0 = out + row0 * D;
        float* o1 = o0 + D;
        #pragma unroll
        for (int k = 0; k < 8; k++) {
            const int d = lane + 32 * k;
            o0[d] = fmaf((y0[k] - mu0) * r0v, gs[d], bs[d]);
            o1[d] = fmaf((y1[k] - mu1) * r1v, gs[d], bs[d]);
        }
    }
}

extern "C" void kernel_launch(void* const* d_in, const int* in_sizes, int n_in,
                              void* d_out, int out_size) {
    const float* x     = (const float*)d_in[0];
    const float* A     = (const float*)d_in[1];
    const float* Bm    = (const float*)d_in[2];
    const float* Cm    = (const float*)d_in[3];
    const float* Dv    = (const float*)d_in[4];
    const float* gamma = (const float*)d_in[5];
    const float* beta  = (const float*)d_in[6];
    float* out = (float*)d_out;

    kA<<<dim3(NC, Bb), 256>>>(x, A, Bm);
    kC<<<dim3(NC, Bb), 256>>>(x, A, Cm, Dv, gamma, beta, out);
}